// round 13
// baseline (speedup 1.0000x reference)
#include <cuda_runtime.h>
#include <cuda_bf16.h>
#include <cuda_fp16.h>
#include <math.h>
#include <stdint.h>
#include <cstdint>

#define TGTN 2048
#define SRCN 4096
#define DIMN 512
#define NHEAD 8
#define HDIM 64
#define NVOC 32000
#define EXTV 36096

// ---------------- scratch (device globals; no allocation allowed) ----------
__device__ __nv_bfloat16 g_Qb[TGTN * DIMN];                   // 2 MB (L2-resident)
__device__ __nv_bfloat16 g_Kb[SRCN * DIMN];                   // 4 MB (L2-resident)
__device__ unsigned char g_S8[(size_t)NHEAD * TGTN * SRCN];   // 64 MB exp(S/8), fp8 e4m3
__device__ float         g_Z[NHEAD * TGTN];                   // softmax denominators
__device__ float         g_lk[TGTN];                          // log_keep
__device__ float         g_lc[TGTN];                          // log_copy

// ---------------- helpers ---------------------------------------------------
__device__ __forceinline__ float log_sigmoid_f(float x) {
    return fminf(x, 0.0f) - log1pf(expf(-fabsf(x)));
}
__device__ __forceinline__ float warp_sum(float v) {
    #pragma unroll
    for (int o = 16; o > 0; o >>= 1) v += __shfl_xor_sync(0xffffffffu, v, o);
    return v;
}
__device__ __forceinline__ void cp16(uint32_t sm, const void* g) {
    asm volatile("cp.async.cg.shared.global [%0], [%1], 16;\n" :: "r"(sm), "l"(g));
}
#define CP_COMMIT() asm volatile("cp.async.commit_group;\n" ::: "memory")
#define CP_WAIT0()  asm volatile("cp.async.wait_group 0;\n" ::: "memory")
#define CP_WAIT1()  asm volatile("cp.async.wait_group 1;\n" ::: "memory")

__device__ __forceinline__ void mma_tf32(float* c, const unsigned* a, const unsigned* b) {
    asm volatile(
        "mma.sync.aligned.m16n8k8.row.col.f32.tf32.tf32.f32 "
        "{%0,%1,%2,%3},{%4,%5,%6,%7},{%8,%9},{%0,%1,%2,%3};\n"
        : "+f"(c[0]), "+f"(c[1]), "+f"(c[2]), "+f"(c[3])
        : "r"(a[0]), "r"(a[1]), "r"(a[2]), "r"(a[3]), "r"(b[0]), "r"(b[1]));
}
__device__ __forceinline__ void mma_bf16(float* c, const unsigned* a, const unsigned* b) {
    asm volatile(
        "mma.sync.aligned.m16n8k16.row.col.f32.bf16.bf16.f32 "
        "{%0,%1,%2,%3},{%4,%5,%6,%7},{%8,%9},{%0,%1,%2,%3};\n"
        : "+f"(c[0]), "+f"(c[1]), "+f"(c[2]), "+f"(c[3])
        : "r"(a[0]), "r"(a[1]), "r"(a[2]), "r"(a[3]), "r"(b[0]), "r"(b[1]));
}
__device__ __forceinline__ void ldsm_x4(unsigned& r0, unsigned& r1, unsigned& r2,
                                        unsigned& r3, uint32_t addr) {
    asm volatile("ldmatrix.sync.aligned.m8n8.x4.shared.b16 {%0,%1,%2,%3}, [%4];\n"
                 : "=r"(r0), "=r"(r1), "=r"(r2), "=r"(r3) : "r"(addr));
}
// pack two f32 -> fp8x2 (e4m3, satfinite); low byte = first arg
__device__ __forceinline__ unsigned short f2e4m3x2(float lo, float hi) {
    unsigned short p;
    asm("cvt.rn.satfinite.e4m3x2.f32 %0, %1, %2;" : "=h"(p) : "f"(hi), "f"(lo));
    return p;
}
// unpack fp8x2 -> float2
__device__ __forceinline__ float2 e4m3x2_2f(unsigned short p) {
    uint32_t h2;
    asm("cvt.rn.f16x2.e4m3x2 %0, %1;" : "=r"(h2) : "h"(p));
    return __half22float2(*(__half2*)&h2);
}

// swizzled 128x64-bf16 tile via cp.async: row pitch 128B, chunk ^= (row&7)
__device__ __forceinline__ void load_tile_ca(const __nv_bfloat16* __restrict__ g,
                                             uint32_t smBase, int tid) {
    #pragma unroll
    for (int it = 0; it < 4; it++) {
        int row = it * 32 + (tid >> 3);
        int c   = tid & 7;
        cp16(smBase + row * 128 + ((c ^ (row & 7)) * 16),
             g + (size_t)row * DIMN + c * 8);
    }
}
__device__ __forceinline__ uint32_t tile_addr(uint32_t base, int row0, int k0, int lane) {
    int r     = row0 + (lane & 15);
    int chunk = (k0 >> 3) + (lane >> 4);
    return base + r * 128 + ((chunk ^ (r & 7)) * 16);
}
// acc[4][4][4] += Q_tile(128x64) @ K_tile(128x64)^T  (warp tile 64x32)
__device__ __forceinline__ void mma_tile(float acc[4][4][4], uint32_t qb, uint32_t kb,
                                         int wm, int wn, int lane) {
    #pragma unroll
    for (int k0 = 0; k0 < HDIM; k0 += 16) {
        unsigned a[4][4], b[4][2];
        #pragma unroll
        for (int mi = 0; mi < 4; mi++)
            ldsm_x4(a[mi][0], a[mi][1], a[mi][2], a[mi][3],
                    tile_addr(qb, wm * 64 + mi * 16, k0, lane));
        #pragma unroll
        for (int nj = 0; nj < 2; nj++) {
            unsigned t0, t1, t2, t3;
            ldsm_x4(t0, t1, t2, t3, tile_addr(kb, wn * 32 + nj * 16, k0, lane));
            b[2 * nj][0]     = t0; b[2 * nj][1]     = t2;
            b[2 * nj + 1][0] = t1; b[2 * nj + 1][1] = t3;
        }
        #pragma unroll
        for (int mi = 0; mi < 4; mi++)
            #pragma unroll
            for (int ni = 0; ni < 4; ni++)
                mma_bf16(acc[mi][ni], a[mi], b[ni]);
    }
}

// ---------------- kernel 1: z / log_copy / log_keep + zero Z ----------------
__global__ void __launch_bounds__(256) z_kernel(
    const float* __restrict__ tgt, const float* __restrict__ w_lin,
    const float* __restrict__ b_lin)
{
    int gidx = blockIdx.x * 256 + threadIdx.x;
    if (gidx < NHEAD * TGTN) g_Z[gidx] = 0.0f;

    int row  = blockIdx.x * 8 + (threadIdx.x >> 5);
    int lane = threadIdx.x & 31;
    if (row >= TGTN) return;
    const float* tp = tgt + (size_t)row * DIMN;
    float s = 0.0f;
    #pragma unroll
    for (int i = 0; i < DIMN / 32; i++) s += tp[lane + i * 32] * w_lin[lane + i * 32];
    s = warp_sum(s);
    if (lane == 0) {
        float z = s + b_lin[0];
        g_lc[row] = log_sigmoid_f(z);
        g_lk[row] = log_sigmoid_f(-z);
    }
}

// ---------------- kernel 2: fused projection GEMMs (tf32 mma, cp.async) -----
__global__ void __launch_bounds__(256, 2) proj_gemm_fused(
    const float* __restrict__ tgt, const float* __restrict__ src,
    const float* __restrict__ Wq,  const float* __restrict__ Wk,
    __nv_bfloat16* __restrict__ pQ, __nv_bfloat16* __restrict__ pK)
{
    __shared__ float As[2][128 * 36];
    __shared__ float Ws[2][32 * 136];

    const bool isK = blockIdx.y >= 16;
    const float* A = isK ? src : tgt;
    const float* W = isK ? Wk  : Wq;
    __nv_bfloat16* C = isK ? pK : pQ;
    const int r0 = (isK ? (blockIdx.y - 16) : blockIdx.y) * 128;
    const int c0 = blockIdx.x * 128;

    const int tid    = threadIdx.x;
    const int lane   = tid & 31;
    const int wid    = tid >> 5;
    const int warp_m = wid & 1;
    const int warp_n = wid >> 1;
    const int g      = lane >> 2;
    const int tg     = lane & 3;

    const uint32_t asB = (uint32_t)__cvta_generic_to_shared(&As[0][0]);
    const uint32_t wsB = (uint32_t)__cvta_generic_to_shared(&Ws[0][0]);
    const uint32_t asPitch = 128 * 36 * 4;
    const uint32_t wsPitch = 32 * 136 * 4;

    const int ar  = tid >> 3, ac4 = tid & 7;
    const int wkr = tid >> 5, wc4 = tid & 31;

    {
        #pragma unroll
        for (int t = 0; t < 4; t++) {
            int r = ar + t * 32;
            cp16(asB + r * 144 + ac4 * 16, &A[(size_t)(r0 + r) * DIMN + ac4 * 4]);
        }
        #pragma unroll
        for (int t = 0; t < 4; t++) {
            int kr = wkr + t * 8;
            cp16(wsB + kr * 544 + wc4 * 16, &W[(size_t)kr * DIMN + c0 + wc4 * 4]);
        }
        CP_COMMIT();
    }

    float acc[4][4][4];
    #pragma unroll
    for (int i = 0; i < 4; i++)
        #pragma unroll
        for (int j = 0; j < 4; j++)
            #pragma unroll
            for (int q = 0; q < 4; q++) acc[i][j][q] = 0.0f;

    #pragma unroll 1
    for (int it = 0; it < DIMN / 32; it++) {
        CP_WAIT0();
        __syncthreads();
        const int cur = it & 1;

        if (it + 1 < DIMN / 32) {
            const int nxt = cur ^ 1;
            const int kc  = (it + 1) * 32;
            #pragma unroll
            for (int t = 0; t < 4; t++) {
                int r = ar + t * 32;
                cp16(asB + nxt * asPitch + r * 144 + ac4 * 16,
                     &A[(size_t)(r0 + r) * DIMN + kc + ac4 * 4]);
            }
            #pragma unroll
            for (int t = 0; t < 4; t++) {
                int kr = wkr + t * 8;
                cp16(wsB + nxt * wsPitch + kr * 544 + wc4 * 16,
                     &W[(size_t)(kc + kr) * DIMN + c0 + wc4 * 4]);
            }
            CP_COMMIT();
        }

        const float* Ab = As[cur];
        const float* Wb = Ws[cur];
        #pragma unroll
        for (int k0 = 0; k0 < 32; k0 += 8) {
            unsigned a[4][4], b[4][2];
            #pragma unroll
            for (int mi = 0; mi < 4; mi++) {
                int mb = warp_m * 64 + mi * 16;
                a[mi][0] = __float_as_uint(Ab[(mb + g    ) * 36 + k0 + tg    ]);
                a[mi][1] = __float_as_uint(Ab[(mb + g + 8) * 36 + k0 + tg    ]);
                a[mi][2] = __float_as_uint(Ab[(mb + g    ) * 36 + k0 + tg + 4]);
                a[mi][3] = __float_as_uint(Ab[(mb + g + 8) * 36 + k0 + tg + 4]);
            }
            #pragma unroll
            for (int ni = 0; ni < 4; ni++) {
                int nb = warp_n * 32 + ni * 8;
                b[ni][0] = __float_as_uint(Wb[(k0 + tg    ) * 136 + nb + g]);
                b[ni][1] = __float_as_uint(Wb[(k0 + tg + 4) * 136 + nb + g]);
            }
            #pragma unroll
            for (int mi = 0; mi < 4; mi++)
                #pragma unroll
                for (int ni = 0; ni < 4; ni++)
                    mma_tf32(acc[mi][ni], a[mi], b[ni]);
        }
        __syncthreads();
    }

    #pragma unroll
    for (int mi = 0; mi < 4; mi++) {
        int r = r0 + warp_m * 64 + mi * 16 + g;
        #pragma unroll
        for (int ni = 0; ni < 4; ni++) {
            int c = c0 + warp_n * 32 + ni * 8 + tg * 2;
            *(__nv_bfloat162*)&C[(size_t)r * DIMN + c] =
                __floats2bfloat162_rn(acc[mi][ni][0], acc[mi][ni][1]);
            *(__nv_bfloat162*)&C[(size_t)(r + 8) * DIMN + c] =
                __floats2bfloat162_rn(acc[mi][ni][2], acc[mi][ni][3]);
        }
    }
}

// ---------------- kernel 3: scores -> exp(S/8) fp8 + Z row sums -------------
// grid (8 s-quads, 16 t-tiles, 8 heads); block 256. Each block: Q loaded once,
// 4 K-tiles streamed through a 2-buffer cp.async pipeline; K prefetch overlaps
// the previous tile's exp/store epilogue; single zrow reduction at the end.
__global__ void __launch_bounds__(256) scores_exp_kernel()
{
    __shared__ __align__(16) char sQ[128 * 128];
    __shared__ __align__(16) char sK[2][128 * 128];
    __shared__ float zrow[128];

    const int tid  = threadIdx.x;
    const int lane = tid & 31;
    const int wid  = tid >> 5;
    const int wm   = wid & 1;
    const int wn   = wid >> 1;
    const int g    = lane >> 2;
    const int tg   = lane & 3;
    const int bq   = blockIdx.x;          // s-quad: 4 s-tiles
    const int bt   = blockIdx.y;
    const int h    = blockIdx.z;

    const uint32_t qb  = (uint32_t)__cvta_generic_to_shared(sQ);
    const uint32_t kb0 = (uint32_t)__cvta_generic_to_shared(sK[0]);
    const uint32_t kb1 = (uint32_t)__cvta_generic_to_shared(sK[1]);

    const __nv_bfloat16* Kbase = g_Kb + (size_t)(bq * 512) * DIMN + h * HDIM;

    // group0: Q + K0 ; group1: K1
    load_tile_ca(g_Qb + (size_t)(bt * 128) * DIMN + h * HDIM, qb, tid);
    load_tile_ca(Kbase, kb0, tid);
    CP_COMMIT();
    load_tile_ca(Kbase + (size_t)128 * DIMN, kb1, tid);
    CP_COMMIT();

    if (tid < 128) zrow[tid] = 0.0f;

    float zacc[4][2];
    #pragma unroll
    for (int mi = 0; mi < 4; mi++) { zacc[mi][0] = 0.0f; zacc[mi][1] = 0.0f; }

    #pragma unroll
    for (int st = 0; st < 4; st++) {
        if (st < 3) { CP_WAIT1(); } else { CP_WAIT0(); }
        __syncthreads();
        const uint32_t kb = (st & 1) ? kb1 : kb0;

        float acc[4][4][4];
        #pragma unroll
        for (int i = 0; i < 4; i++)
            #pragma unroll
            for (int j = 0; j < 4; j++)
                #pragma unroll
                for (int q = 0; q < 4; q++) acc[i][j][q] = 0.0f;
        mma_tile(acc, qb, kb, wm, wn, lane);
        __syncthreads();               // all warps done reading sK[st&1]

        if (st + 2 < 4) {              // prefetch tile st+2 into the freed buffer
            load_tile_ca(Kbase + (size_t)(st + 2) * 128 * DIMN,
                         (st & 1) ? kb1 : kb0, tid);
            CP_COMMIT();
        }

        // epilogue overlaps the cp.async prefetch
        #pragma unroll
        for (int mi = 0; mi < 4; mi++) {
            int r = bt * 128 + wm * 64 + mi * 16 + g;
            size_t base0 = ((size_t)h * TGTN + r) * SRCN;
            size_t base1 = base0 + (size_t)8 * SRCN;
            #pragma unroll
            for (int ni = 0; ni < 4; ni++) {
                int c = bq * 512 + st * 128 + wn * 32 + ni * 8 + tg * 2;
                float e0 = __expf(acc[mi][ni][0] * 0.125f);
                float e1 = __expf(acc[mi][ni][1] * 0.125f);
                float e2 = __expf(acc[mi][ni][2] * 0.125f);
                float e3 = __expf(acc[mi][ni][3] * 0.125f);
                *(unsigned short*)&g_S8[base0 + c] = f2e4m3x2(e0, e1);
                *(unsigned short*)&g_S8[base1 + c] = f2e4m3x2(e2, e3);
                zacc[mi][0] += e0 + e1;
                zacc[mi][1] += e2 + e3;
            }
        }
    }

    // single zrow reduction for all 4 tiles
    #pragma unroll
    for (int mi = 0; mi < 4; mi++)
        #pragma unroll
        for (int half = 0; half < 2; half++) {
            float v = zacc[mi][half];
            v += __shfl_xor_sync(0xffffffffu, v, 1);
            v += __shfl_xor_sync(0xffffffffu, v, 2);
            if (tg == 0) atomicAdd(&zrow[wm * 64 + mi * 16 + half * 8 + g], v);
        }
    __syncthreads();
    if (tid < 128)
        atomicAdd(&g_Z[h * TGTN + bt * 128 + tid], zrow[tid]);
}

// ---------------- kernel 4: fused attn-combine + scatter + softmax + mix ----
// tail outputs (v >= NVOC, lse-independent) are written right after the
// scatter barrier to balance read/write DRAM demand across the kernel.
__global__ void __launch_bounds__(1024, 2) final_kernel(
    const float* __restrict__ logits, const int* __restrict__ ids,
    float* __restrict__ out)
{
    extern __shared__ char smraw[];
    __nv_bfloat162* ext2 = (__nv_bfloat162*)smraw;              // EXTV/2 pairs
    float* red = (float*)(smraw + EXTV * 2);                    // 32
    float* wsh = red + 32;                                      // 8

    const int t    = blockIdx.x;
    const int tid  = threadIdx.x;
    const int lane = tid & 31;
    const int wid  = tid >> 5;

    // zero ext table (72192 B = 4512 uint4)
    {
        uint4 z4 = make_uint4(0u, 0u, 0u, 0u);
        uint4* e4 = (uint4*)smraw;
        for (int i = tid; i < EXTV * 2 / 16; i += 1024) e4[i] = z4;
    }
    if (tid < NHEAD) wsh[tid] = 0.125f / g_Z[tid * TGTN + t];
    __syncthreads();

    // scatter: SRCN/4 = 1024 -> exactly one 4-wide iteration per thread
    {
        const int i = tid;
        float a0 = 0.0f, a1 = 0.0f, a2 = 0.0f, a3 = 0.0f;
        #pragma unroll
        for (int h = 0; h < NHEAD; h++) {
            const unsigned int* sp =
                (const unsigned int*)(g_S8 + ((size_t)h * TGTN + t) * SRCN);
            unsigned int p = __ldcs(sp + i);
            float2 f01 = e4m3x2_2f((unsigned short)(p & 0xffffu));
            float2 f23 = e4m3x2_2f((unsigned short)(p >> 16));
            float wh = wsh[h];
            a0 = fmaf(f01.x, wh, a0);
            a1 = fmaf(f01.y, wh, a1);
            a2 = fmaf(f23.x, wh, a2);
            a3 = fmaf(f23.y, wh, a3);
        }
        int4 d = ((const int4*)ids)[i];
        atomicAdd(&ext2[d.x >> 1], (d.x & 1) ? __floats2bfloat162_rn(0.0f, a0)
                                             : __floats2bfloat162_rn(a0, 0.0f));
        atomicAdd(&ext2[d.y >> 1], (d.y & 1) ? __floats2bfloat162_rn(0.0f, a1)
                                             : __floats2bfloat162_rn(a1, 0.0f));
        atomicAdd(&ext2[d.z >> 1], (d.z & 1) ? __floats2bfloat162_rn(0.0f, a2)
                                             : __floats2bfloat162_rn(a2, 0.0f));
        atomicAdd(&ext2[d.w >> 1], (d.w & 1) ? __floats2bfloat162_rn(0.0f, a3)
                                             : __floats2bfloat162_rn(a3, 0.0f));
    }
    __syncthreads();                 // ext table final

    const float copyp = __expf(g_lc[t]);
    const float lk    = g_lk[t];
    const uint2* extv = (const uint2*)smraw;     // 4 bf16 per uint2
    float4* op4 = (float4*)(out + (size_t)t * EXTV);

    // tail outputs first (v >= NVOC): exactly 1024 float4 -> one per thread;
    // lse-independent, starts the store stream early.
    {
        const int i = NVOC / 4 + tid;            // [8000, 9024)
        uint2 ee = extv[i];
        float2 f01 = __bfloat1622float2(*(__nv_bfloat162*)&ee.x);
        float2 f23 = __bfloat1622float2(*(__nv_bfloat162*)&ee.y);
        float4 o;
        o.x = (f01.x > 0.0f) ? __logf(f01.x * copyp) : -1e9f;
        o.y = (f01.y > 0.0f) ? __logf(f01.y * copyp) : -1e9f;
        o.z = (f23.x > 0.0f) ? __logf(f23.x * copyp) : -1e9f;
        o.w = (f23.y > 0.0f) ? __logf(f23.y * copyp) : -1e9f;
        __stcs(op4 + i, o);
    }

    // pass 1: sum of exp over logits (bounded; no max pass), float4 loads
    const float4* lg4 = (const float4*)(logits + (size_t)t * NVOC);
    float s0 = 0.0f, s1 = 0.0f;
    #pragma unroll 4
    for (int i = tid; i < NVOC / 4; i += 1024) {
        float4 x = lg4[i];
        s0 += __expf(x.x) + __expf(x.y);
        s1 += __expf(x.z) + __expf(x.w);
    }
    float ssum = warp_sum(s0 + s1);
    if (lane == 0) red[wid] = ssum;
    __syncthreads();
    if (wid == 0) {
        float x = red[lane];
        x = warp_sum(x);
        if (lane == 0) red[0] = x;
    }
    __syncthreads();
    const float lse = __logf(red[0]);

    // pass 2: main outputs (v < NVOC); logits .cs (last use), out .cs
    #pragma unroll 4
    for (int i = tid; i < NVOC / 4; i += 1024) {
        uint2 ee = extv[i];
        float4 x = __ldcs(lg4 + i);
        float2 f01 = __bfloat1622float2(*(__nv_bfloat162*)&ee.x);
        float2 f23 = __bfloat1622float2(*(__nv_bfloat162*)&ee.y);
        float b0 = x.x - lse + lk, b1 = x.y - lse + lk;
        float b2 = x.z - lse + lk, b3 = x.w - lse + lk;
        float4 o;
        o.x = (f01.x > 0.0f) ? __logf(__expf(b0) + f01.x * copyp) : b0;
        o.y = (f01.y > 0.0f) ? __logf(__expf(b1) + f01.y * copyp) : b1;
        o.z = (f23.x > 0.0f) ? __logf(__expf(b2) + f23.x * copyp) : b2;
        o.w = (f23.y > 0.0f) ? __logf(__expf(b3) + f23.y * copyp) : b3;
        __stcs(op4 + i, o);
    }
}

// ---------------- host launcher ---------------------------------------------
extern "C" void kernel_launch(void* const* d_in, const int* in_sizes, int n_in,
                              void* d_out, int out_size)
{
    const float* logits = (const float*)d_in[0];
    const int*   ids    = (const int*)d_in[1];
    const float* src    = (const float*)d_in[2];
    const float* tgt    = (const float*)d_in[3];
    const float* w_lin;
    const float* b_lin;
    const float* Wq;
    const float* Wk;
    if (n_in >= 9 && in_sizes[4] == 1) {
        w_lin = (const float*)d_in[5];
        b_lin = (const float*)d_in[6];
        Wq    = (const float*)d_in[7];
        Wk    = (const float*)d_in[8];
    } else {
        w_lin = (const float*)d_in[4];
        b_lin = (const float*)d_in[5];
        Wq    = (const float*)d_in[6];
        Wk    = (const float*)d_in[7];
    }

    static const int FINAL_SMEM = EXTV * 2 + 40 * 4;   // 72,352 B

    static bool            inited = false;
    static __nv_bfloat16*  pQ = nullptr;
    static __nv_bfloat16*  pK = nullptr;
    if (!inited) {
        cudaFuncSetAttribute(final_kernel,
                             cudaFuncAttributeMaxDynamicSharedMemorySize,
                             FINAL_SMEM);
        void* tmp;
        cudaGetSymbolAddress(&tmp, g_Qb); pQ = (__nv_bfloat16*)tmp;
        cudaGetSymbolAddress(&tmp, g_Kb); pK = (__nv_bfloat16*)tmp;
        inited = true;
    }

    float* out = (float*)d_out;

    // 1) gating scalars + Z zeroing (fused)
    z_kernel<<<TGTN / 8, 256>>>(tgt, w_lin, b_lin);

    // 2) both projections in one launch (tf32 mma, cp.async pipeline)
    proj_gemm_fused<<<dim3(DIMN / 128, 48), 256>>>(tgt, src, Wq, Wk, pQ, pK);

    // 3) per-head exp-scores: 4 s-tiles/block, double-buffered K pipeline
    scores_exp_kernel<<<dim3(SRCN / 512, TGTN / 128, NHEAD), 256>>>();

    // 4) fused head-combine + scatter + log_softmax + logaddexp
    final_kernel<<<TGTN, 1024, FINAL_SMEM>>>(logits, ids, out);
}

// round 14
// speedup vs baseline: 1.0455x; 1.0455x over previous
#include <cuda_runtime.h>
#include <cuda_bf16.h>
#include <cuda_fp16.h>
#include <math.h>
#include <stdint.h>
#include <cstdint>

#define TGTN 2048
#define SRCN 4096
#define DIMN 512
#define NHEAD 8
#define HDIM 64
#define NVOC 32000
#define EXTV 36096

// ---------------- scratch (device globals; no allocation allowed) ----------
__device__ __nv_bfloat16 g_Qb[TGTN * DIMN];                   // 2 MB (L2-resident)
__device__ __nv_bfloat16 g_Kb[SRCN * DIMN];                   // 4 MB (L2-resident)
__device__ unsigned char g_S8[(size_t)NHEAD * TGTN * SRCN];   // 64 MB exp(S/8), fp8 e4m3
__device__ float         g_Z[NHEAD * TGTN];                   // softmax denominators
__device__ float         g_lk[TGTN];                          // log_keep
__device__ float         g_lc[TGTN];                          // log_copy

// ---------------- helpers ---------------------------------------------------
__device__ __forceinline__ float log_sigmoid_f(float x) {
    return fminf(x, 0.0f) - log1pf(expf(-fabsf(x)));
}
__device__ __forceinline__ float warp_sum(float v) {
    #pragma unroll
    for (int o = 16; o > 0; o >>= 1) v += __shfl_xor_sync(0xffffffffu, v, o);
    return v;
}
__device__ __forceinline__ void cp16(uint32_t sm, const void* g) {
    asm volatile("cp.async.cg.shared.global [%0], [%1], 16;\n" :: "r"(sm), "l"(g));
}
#define CP_COMMIT() asm volatile("cp.async.commit_group;\n" ::: "memory")
#define CP_WAIT0()  asm volatile("cp.async.wait_group 0;\n" ::: "memory")

__device__ __forceinline__ void mma_tf32(float* c, const unsigned* a, const unsigned* b) {
    asm volatile(
        "mma.sync.aligned.m16n8k8.row.col.f32.tf32.tf32.f32 "
        "{%0,%1,%2,%3},{%4,%5,%6,%7},{%8,%9},{%0,%1,%2,%3};\n"
        : "+f"(c[0]), "+f"(c[1]), "+f"(c[2]), "+f"(c[3])
        : "r"(a[0]), "r"(a[1]), "r"(a[2]), "r"(a[3]), "r"(b[0]), "r"(b[1]));
}
__device__ __forceinline__ void mma_bf16(float* c, const unsigned* a, const unsigned* b) {
    asm volatile(
        "mma.sync.aligned.m16n8k16.row.col.f32.bf16.bf16.f32 "
        "{%0,%1,%2,%3},{%4,%5,%6,%7},{%8,%9},{%0,%1,%2,%3};\n"
        : "+f"(c[0]), "+f"(c[1]), "+f"(c[2]), "+f"(c[3])
        : "r"(a[0]), "r"(a[1]), "r"(a[2]), "r"(a[3]), "r"(b[0]), "r"(b[1]));
}
__device__ __forceinline__ void ldsm_x4(unsigned& r0, unsigned& r1, unsigned& r2,
                                        unsigned& r3, uint32_t addr) {
    asm volatile("ldmatrix.sync.aligned.m8n8.x4.shared.b16 {%0,%1,%2,%3}, [%4];\n"
                 : "=r"(r0), "=r"(r1), "=r"(r2), "=r"(r3) : "r"(addr));
}
// pack two f32 -> fp8x2 (e4m3, satfinite); low byte = first arg
__device__ __forceinline__ unsigned short f2e4m3x2(float lo, float hi) {
    unsigned short p;
    asm("cvt.rn.satfinite.e4m3x2.f32 %0, %1, %2;" : "=h"(p) : "f"(hi), "f"(lo));
    return p;
}
// unpack fp8x2 -> float2
__device__ __forceinline__ float2 e4m3x2_2f(unsigned short p) {
    uint32_t h2;
    asm("cvt.rn.f16x2.e4m3x2 %0, %1;" : "=r"(h2) : "h"(p));
    return __half22float2(*(__half2*)&h2);
}

// swizzled 128x64-bf16 tile via cp.async: row pitch 128B, chunk ^= (row&7)
__device__ __forceinline__ void load_tile_ca(const __nv_bfloat16* __restrict__ g,
                                             uint32_t smBase, int tid) {
    #pragma unroll
    for (int it = 0; it < 4; it++) {
        int row = it * 32 + (tid >> 3);
        int c   = tid & 7;
        cp16(smBase + row * 128 + ((c ^ (row & 7)) * 16),
             g + (size_t)row * DIMN + c * 8);
    }
}
__device__ __forceinline__ uint32_t tile_addr(uint32_t base, int row0, int k0, int lane) {
    int r     = row0 + (lane & 15);
    int chunk = (k0 >> 3) + (lane >> 4);
    return base + r * 128 + ((chunk ^ (r & 7)) * 16);
}
// acc[4][4][4] += Q_tile(128x64) @ K_tile(128x64)^T  (warp tile 64x32)
__device__ __forceinline__ void mma_tile(float acc[4][4][4], uint32_t qb, uint32_t kb,
                                         int wm, int wn, int lane) {
    #pragma unroll
    for (int k0 = 0; k0 < HDIM; k0 += 16) {
        unsigned a[4][4], b[4][2];
        #pragma unroll
        for (int mi = 0; mi < 4; mi++)
            ldsm_x4(a[mi][0], a[mi][1], a[mi][2], a[mi][3],
                    tile_addr(qb, wm * 64 + mi * 16, k0, lane));
        #pragma unroll
        for (int nj = 0; nj < 2; nj++) {
            unsigned t0, t1, t2, t3;
            ldsm_x4(t0, t1, t2, t3, tile_addr(kb, wn * 32 + nj * 16, k0, lane));
            b[2 * nj][0]     = t0; b[2 * nj][1]     = t2;
            b[2 * nj + 1][0] = t1; b[2 * nj + 1][1] = t3;
        }
        #pragma unroll
        for (int mi = 0; mi < 4; mi++)
            #pragma unroll
            for (int ni = 0; ni < 4; ni++)
                mma_bf16(acc[mi][ni], a[mi], b[ni]);
    }
}

// ---------------- kernel 1: z / log_copy / log_keep + zero Z ----------------
__global__ void __launch_bounds__(256) z_kernel(
    const float* __restrict__ tgt, const float* __restrict__ w_lin,
    const float* __restrict__ b_lin)
{
    int gidx = blockIdx.x * 256 + threadIdx.x;
    if (gidx < NHEAD * TGTN) g_Z[gidx] = 0.0f;

    int row  = blockIdx.x * 8 + (threadIdx.x >> 5);
    int lane = threadIdx.x & 31;
    if (row >= TGTN) return;
    const float* tp = tgt + (size_t)row * DIMN;
    float s = 0.0f;
    #pragma unroll
    for (int i = 0; i < DIMN / 32; i++) s += tp[lane + i * 32] * w_lin[lane + i * 32];
    s = warp_sum(s);
    if (lane == 0) {
        float z = s + b_lin[0];
        g_lc[row] = log_sigmoid_f(z);
        g_lk[row] = log_sigmoid_f(-z);
    }
}

// ---------------- kernel 2: fused projection GEMMs (tf32 mma, cp.async) -----
__global__ void __launch_bounds__(256, 2) proj_gemm_fused(
    const float* __restrict__ tgt, const float* __restrict__ src,
    const float* __restrict__ Wq,  const float* __restrict__ Wk,
    __nv_bfloat16* __restrict__ pQ, __nv_bfloat16* __restrict__ pK)
{
    __shared__ float As[2][128 * 36];
    __shared__ float Ws[2][32 * 136];

    const bool isK = blockIdx.y >= 16;
    const float* A = isK ? src : tgt;
    const float* W = isK ? Wk  : Wq;
    __nv_bfloat16* C = isK ? pK : pQ;
    const int r0 = (isK ? (blockIdx.y - 16) : blockIdx.y) * 128;
    const int c0 = blockIdx.x * 128;

    const int tid    = threadIdx.x;
    const int lane   = tid & 31;
    const int wid    = tid >> 5;
    const int warp_m = wid & 1;
    const int warp_n = wid >> 1;
    const int g      = lane >> 2;
    const int tg     = lane & 3;

    const uint32_t asB = (uint32_t)__cvta_generic_to_shared(&As[0][0]);
    const uint32_t wsB = (uint32_t)__cvta_generic_to_shared(&Ws[0][0]);
    const uint32_t asPitch = 128 * 36 * 4;
    const uint32_t wsPitch = 32 * 136 * 4;

    const int ar  = tid >> 3, ac4 = tid & 7;
    const int wkr = tid >> 5, wc4 = tid & 31;

    {
        #pragma unroll
        for (int t = 0; t < 4; t++) {
            int r = ar + t * 32;
            cp16(asB + r * 144 + ac4 * 16, &A[(size_t)(r0 + r) * DIMN + ac4 * 4]);
        }
        #pragma unroll
        for (int t = 0; t < 4; t++) {
            int kr = wkr + t * 8;
            cp16(wsB + kr * 544 + wc4 * 16, &W[(size_t)kr * DIMN + c0 + wc4 * 4]);
        }
        CP_COMMIT();
    }

    float acc[4][4][4];
    #pragma unroll
    for (int i = 0; i < 4; i++)
        #pragma unroll
        for (int j = 0; j < 4; j++)
            #pragma unroll
            for (int q = 0; q < 4; q++) acc[i][j][q] = 0.0f;

    #pragma unroll 1
    for (int it = 0; it < DIMN / 32; it++) {
        CP_WAIT0();
        __syncthreads();
        const int cur = it & 1;

        if (it + 1 < DIMN / 32) {
            const int nxt = cur ^ 1;
            const int kc  = (it + 1) * 32;
            #pragma unroll
            for (int t = 0; t < 4; t++) {
                int r = ar + t * 32;
                cp16(asB + nxt * asPitch + r * 144 + ac4 * 16,
                     &A[(size_t)(r0 + r) * DIMN + kc + ac4 * 4]);
            }
            #pragma unroll
            for (int t = 0; t < 4; t++) {
                int kr = wkr + t * 8;
                cp16(wsB + nxt * wsPitch + kr * 544 + wc4 * 16,
                     &W[(size_t)(kc + kr) * DIMN + c0 + wc4 * 4]);
            }
            CP_COMMIT();
        }

        const float* Ab = As[cur];
        const float* Wb = Ws[cur];
        #pragma unroll
        for (int k0 = 0; k0 < 32; k0 += 8) {
            unsigned a[4][4], b[4][2];
            #pragma unroll
            for (int mi = 0; mi < 4; mi++) {
                int mb = warp_m * 64 + mi * 16;
                a[mi][0] = __float_as_uint(Ab[(mb + g    ) * 36 + k0 + tg    ]);
                a[mi][1] = __float_as_uint(Ab[(mb + g + 8) * 36 + k0 + tg    ]);
                a[mi][2] = __float_as_uint(Ab[(mb + g    ) * 36 + k0 + tg + 4]);
                a[mi][3] = __float_as_uint(Ab[(mb + g + 8) * 36 + k0 + tg + 4]);
            }
            #pragma unroll
            for (int ni = 0; ni < 4; ni++) {
                int nb = warp_n * 32 + ni * 8;
                b[ni][0] = __float_as_uint(Wb[(k0 + tg    ) * 136 + nb + g]);
                b[ni][1] = __float_as_uint(Wb[(k0 + tg + 4) * 136 + nb + g]);
            }
            #pragma unroll
            for (int mi = 0; mi < 4; mi++)
                #pragma unroll
                for (int ni = 0; ni < 4; ni++)
                    mma_tf32(acc[mi][ni], a[mi], b[ni]);
        }
        __syncthreads();
    }

    #pragma unroll
    for (int mi = 0; mi < 4; mi++) {
        int r = r0 + warp_m * 64 + mi * 16 + g;
        #pragma unroll
        for (int ni = 0; ni < 4; ni++) {
            int c = c0 + warp_n * 32 + ni * 8 + tg * 2;
            *(__nv_bfloat162*)&C[(size_t)r * DIMN + c] =
                __floats2bfloat162_rn(acc[mi][ni][0], acc[mi][ni][1]);
            *(__nv_bfloat162*)&C[(size_t)(r + 8) * DIMN + c] =
                __floats2bfloat162_rn(acc[mi][ni][2], acc[mi][ni][3]);
        }
    }
}

// ---------------- kernel 3: scores -> exp(S/8) fp8 + Z row sums -------------
// grid (32 s-tiles, 16 t-tiles, 8 heads); block 256 (warps 2x4, 64x32 tile).
// (R12 version — measured faster than the 4-tile pipelined variant.)
__global__ void __launch_bounds__(256) scores_exp_kernel()
{
    __shared__ __align__(16) char sQ[128 * 128];
    __shared__ __align__(16) char sK[128 * 128];
    __shared__ float zrow[128];

    const int tid  = threadIdx.x;
    const int lane = tid & 31;
    const int wid  = tid >> 5;
    const int wm   = wid & 1;
    const int wn   = wid >> 1;
    const int g    = lane >> 2;
    const int tg   = lane & 3;
    const int bs   = blockIdx.x;
    const int bt   = blockIdx.y;
    const int h    = blockIdx.z;

    const uint32_t qb = (uint32_t)__cvta_generic_to_shared(sQ);
    const uint32_t kb = (uint32_t)__cvta_generic_to_shared(sK);

    load_tile_ca(g_Qb + (size_t)(bt * 128) * DIMN + h * HDIM, qb, tid);
    load_tile_ca(g_Kb + (size_t)(bs * 128) * DIMN + h * HDIM, kb, tid);
    CP_COMMIT();
    if (tid < 128) zrow[tid] = 0.0f;
    CP_WAIT0();
    __syncthreads();

    float acc[4][4][4];
    #pragma unroll
    for (int i = 0; i < 4; i++)
        #pragma unroll
        for (int j = 0; j < 4; j++)
            #pragma unroll
            for (int q = 0; q < 4; q++) acc[i][j][q] = 0.0f;
    mma_tile(acc, qb, kb, wm, wn, lane);

    float zacc[4][2];
    #pragma unroll
    for (int mi = 0; mi < 4; mi++) { zacc[mi][0] = 0.0f; zacc[mi][1] = 0.0f; }

    #pragma unroll
    for (int mi = 0; mi < 4; mi++) {
        int r = bt * 128 + wm * 64 + mi * 16 + g;
        size_t base0 = ((size_t)h * TGTN + r) * SRCN;
        size_t base1 = base0 + (size_t)8 * SRCN;
        #pragma unroll
        for (int ni = 0; ni < 4; ni++) {
            int c = bs * 128 + wn * 32 + ni * 8 + tg * 2;
            float e0 = __expf(acc[mi][ni][0] * 0.125f);
            float e1 = __expf(acc[mi][ni][1] * 0.125f);
            float e2 = __expf(acc[mi][ni][2] * 0.125f);
            float e3 = __expf(acc[mi][ni][3] * 0.125f);
            *(unsigned short*)&g_S8[base0 + c] = f2e4m3x2(e0, e1);
            *(unsigned short*)&g_S8[base1 + c] = f2e4m3x2(e2, e3);
            zacc[mi][0] += e0 + e1;
            zacc[mi][1] += e2 + e3;
        }
    }

    #pragma unroll
    for (int mi = 0; mi < 4; mi++)
        #pragma unroll
        for (int half = 0; half < 2; half++) {
            float v = zacc[mi][half];
            v += __shfl_xor_sync(0xffffffffu, v, 1);
            v += __shfl_xor_sync(0xffffffffu, v, 2);
            if (tg == 0) atomicAdd(&zrow[wm * 64 + mi * 16 + half * 8 + g], v);
        }
    __syncthreads();
    if (tid < 128)
        atomicAdd(&g_Z[h * TGTN + bt * 128 + tid], zrow[tid]);
}

// ---------------- kernel 4: fused attn-combine + scatter + softmax + mix ----
// tail outputs (v >= NVOC, lse-independent) are written right after the
// scatter barrier to balance read/write DRAM demand across the kernel.
__global__ void __launch_bounds__(1024, 2) final_kernel(
    const float* __restrict__ logits, const int* __restrict__ ids,
    float* __restrict__ out)
{
    extern __shared__ char smraw[];
    __nv_bfloat162* ext2 = (__nv_bfloat162*)smraw;              // EXTV/2 pairs
    float* red = (float*)(smraw + EXTV * 2);                    // 32
    float* wsh = red + 32;                                      // 8

    const int t    = blockIdx.x;
    const int tid  = threadIdx.x;
    const int lane = tid & 31;
    const int wid  = tid >> 5;

    // zero ext table (72192 B = 4512 uint4)
    {
        uint4 z4 = make_uint4(0u, 0u, 0u, 0u);
        uint4* e4 = (uint4*)smraw;
        for (int i = tid; i < EXTV * 2 / 16; i += 1024) e4[i] = z4;
    }
    if (tid < NHEAD) wsh[tid] = 0.125f / g_Z[tid * TGTN + t];
    __syncthreads();

    // scatter: SRCN/4 = 1024 -> exactly one 4-wide iteration per thread
    {
        const int i = tid;
        float a0 = 0.0f, a1 = 0.0f, a2 = 0.0f, a3 = 0.0f;
        #pragma unroll
        for (int h = 0; h < NHEAD; h++) {
            const unsigned int* sp =
                (const unsigned int*)(g_S8 + ((size_t)h * TGTN + t) * SRCN);
            unsigned int p = __ldcs(sp + i);
            float2 f01 = e4m3x2_2f((unsigned short)(p & 0xffffu));
            float2 f23 = e4m3x2_2f((unsigned short)(p >> 16));
            float wh = wsh[h];
            a0 = fmaf(f01.x, wh, a0);
            a1 = fmaf(f01.y, wh, a1);
            a2 = fmaf(f23.x, wh, a2);
            a3 = fmaf(f23.y, wh, a3);
        }
        int4 d = ((const int4*)ids)[i];
        atomicAdd(&ext2[d.x >> 1], (d.x & 1) ? __floats2bfloat162_rn(0.0f, a0)
                                             : __floats2bfloat162_rn(a0, 0.0f));
        atomicAdd(&ext2[d.y >> 1], (d.y & 1) ? __floats2bfloat162_rn(0.0f, a1)
                                             : __floats2bfloat162_rn(a1, 0.0f));
        atomicAdd(&ext2[d.z >> 1], (d.z & 1) ? __floats2bfloat162_rn(0.0f, a2)
                                             : __floats2bfloat162_rn(a2, 0.0f));
        atomicAdd(&ext2[d.w >> 1], (d.w & 1) ? __floats2bfloat162_rn(0.0f, a3)
                                             : __floats2bfloat162_rn(a3, 0.0f));
    }
    __syncthreads();                 // ext table final

    const float copyp = __expf(g_lc[t]);
    const float lk    = g_lk[t];
    const uint2* extv = (const uint2*)smraw;     // 4 bf16 per uint2
    float4* op4 = (float4*)(out + (size_t)t * EXTV);

    // tail outputs first (v >= NVOC): exactly 1024 float4 -> one per thread;
    // lse-independent, starts the store stream early.
    {
        const int i = NVOC / 4 + tid;            // [8000, 9024)
        uint2 ee = extv[i];
        float2 f01 = __bfloat1622float2(*(__nv_bfloat162*)&ee.x);
        float2 f23 = __bfloat1622float2(*(__nv_bfloat162*)&ee.y);
        float4 o;
        o.x = (f01.x > 0.0f) ? __logf(f01.x * copyp) : -1e9f;
        o.y = (f01.y > 0.0f) ? __logf(f01.y * copyp) : -1e9f;
        o.z = (f23.x > 0.0f) ? __logf(f23.x * copyp) : -1e9f;
        o.w = (f23.y > 0.0f) ? __logf(f23.y * copyp) : -1e9f;
        __stcs(op4 + i, o);
    }

    // pass 1: sum of exp over logits (bounded; no max pass), float4 loads
    const float4* lg4 = (const float4*)(logits + (size_t)t * NVOC);
    float s0 = 0.0f, s1 = 0.0f;
    #pragma unroll 4
    for (int i = tid; i < NVOC / 4; i += 1024) {
        float4 x = lg4[i];
        s0 += __expf(x.x) + __expf(x.y);
        s1 += __expf(x.z) + __expf(x.w);
    }
    float ssum = warp_sum(s0 + s1);
    if (lane == 0) red[wid] = ssum;
    __syncthreads();
    if (wid == 0) {
        float x = red[lane];
        x = warp_sum(x);
        if (lane == 0) red[0] = x;
    }
    __syncthreads();
    const float lse = __logf(red[0]);

    // pass 2: main outputs (v < NVOC); logits .cs (last use), out .cs
    #pragma unroll 4
    for (int i = tid; i < NVOC / 4; i += 1024) {
        uint2 ee = extv[i];
        float4 x = __ldcs(lg4 + i);
        float2 f01 = __bfloat1622float2(*(__nv_bfloat162*)&ee.x);
        float2 f23 = __bfloat1622float2(*(__nv_bfloat162*)&ee.y);
        float b0 = x.x - lse + lk, b1 = x.y - lse + lk;
        float b2 = x.z - lse + lk, b3 = x.w - lse + lk;
        float4 o;
        o.x = (f01.x > 0.0f) ? __logf(__expf(b0) + f01.x * copyp) : b0;
        o.y = (f01.y > 0.0f) ? __logf(__expf(b1) + f01.y * copyp) : b1;
        o.z = (f23.x > 0.0f) ? __logf(__expf(b2) + f23.x * copyp) : b2;
        o.w = (f23.y > 0.0f) ? __logf(__expf(b3) + f23.y * copyp) : b3;
        __stcs(op4 + i, o);
    }
}

// ---------------- host launcher ---------------------------------------------
extern "C" void kernel_launch(void* const* d_in, const int* in_sizes, int n_in,
                              void* d_out, int out_size)
{
    const float* logits = (const float*)d_in[0];
    const int*   ids    = (const int*)d_in[1];
    const float* src    = (const float*)d_in[2];
    const float* tgt    = (const float*)d_in[3];
    const float* w_lin;
    const float* b_lin;
    const float* Wq;
    const float* Wk;
    if (n_in >= 9 && in_sizes[4] == 1) {
        w_lin = (const float*)d_in[5];
        b_lin = (const float*)d_in[6];
        Wq    = (const float*)d_in[7];
        Wk    = (const float*)d_in[8];
    } else {
        w_lin = (const float*)d_in[4];
        b_lin = (const float*)d_in[5];
        Wq    = (const float*)d_in[6];
        Wk    = (const float*)d_in[7];
    }

    static const int FINAL_SMEM = EXTV * 2 + 40 * 4;   // 72,352 B

    static bool            inited = false;
    static __nv_bfloat16*  pQ = nullptr;
    static __nv_bfloat16*  pK = nullptr;
    if (!inited) {
        cudaFuncSetAttribute(final_kernel,
                             cudaFuncAttributeMaxDynamicSharedMemorySize,
                             FINAL_SMEM);
        void* tmp;
        cudaGetSymbolAddress(&tmp, g_Qb); pQ = (__nv_bfloat16*)tmp;
        cudaGetSymbolAddress(&tmp, g_Kb); pK = (__nv_bfloat16*)tmp;
        inited = true;
    }

    float* out = (float*)d_out;

    // 1) gating scalars + Z zeroing (fused)
    z_kernel<<<TGTN / 8, 256>>>(tgt, w_lin, b_lin);

    // 2) both projections in one launch (tf32 mma, cp.async pipeline)
    proj_gemm_fused<<<dim3(DIMN / 128, 48), 256>>>(tgt, src, Wq, Wk, pQ, pK);

    // 3) per-head exp-scores (R12 single-tile version; measured faster)
    scores_exp_kernel<<<dim3(SRCN / 128, TGTN / 128, NHEAD), 256>>>();

    // 4) fused head-combine + scatter + log_softmax + logaddexp
    final_kernel<<<TGTN, 1024, FINAL_SMEM>>>(logits, ids, out);
}